// round 14
// baseline (speedup 1.0000x reference)
#include <cuda_runtime.h>
#include <cuda_fp16.h>
#include <math.h>
#include <stdint.h>

// Problem constants
#define BB   256
#define TT   512
#define DIN  64
#define HH   1024
#define DOUT 10

// Config: 64 CTAs (4 batch-tiles x 16 h-tiles), tile 64 batch x 64 h-out.
// 256 threads = 2 K-split halves x 4 warps; warp tile 32x32.
// Dataflow sync: per-(t,ib,jb) flags instead of a global barrier; staggered chunk order.
#define GRID 64
#define NTH  256
#define BT   64
#define HT   64
#define KCH  64
#define NIB  4
#define NJB  16

// SMEM layout (bytes)
#define BSTRIDE_H 1096
#define BSTRIDE_B (BSTRIDE_H*2)            // 2192 == 4 mod 32 words -> conflict-free ldsm
#define ASTRIDE_B 144
#define ABUF_B    (BT*ASTRIDE_B)           // 9216
#define SM_B      0
#define SM_B_SZ   (HT*BSTRIDE_B)           // 140288
#define SM_A0     SM_B_SZ
#define SM_AX     (SM_A0 + 4*ABUF_B)
#define SM_A1     (SM_AX + ABUF_B)
#define SM_RED    SM_A1
#define SM_BIAS   (SM_A1 + 4*ABUF_B)       // 223232
#define SMEM_BYTES (SM_BIAS + 256)         // 223488

#define SPIN_BOUND (1u<<20)

// Global scratch
__device__ __align__(256) __half g_h[2][BB][HH];
__device__ __align__(256) __half g_x[TT][BB][DIN];
__device__ __align__(256) unsigned g_flag[TT][NIB][NJB][8];   // padded to 32B/flag

// ---------------- helpers ----------------
__device__ __forceinline__ void cp_async16(void* sptr, const void* gptr) {
    uint32_t s = (uint32_t)__cvta_generic_to_shared(sptr);
    asm volatile("cp.async.cg.shared.global [%0], [%1], 16;" :: "r"(s), "l"(gptr));
}
__device__ __forceinline__ void cp_commit() { asm volatile("cp.async.commit_group;"); }
template<int N> __device__ __forceinline__ void cp_wait() {
    asm volatile("cp.async.wait_group %0;" :: "n"(N));
}
__device__ __forceinline__ void cp_wait_dyn(int n) {
    switch (n) {
    case 0: cp_wait<0>(); break; case 1: cp_wait<1>(); break;
    case 2: cp_wait<2>(); break; case 3: cp_wait<3>(); break;
    default: cp_wait<4>(); break;
    }
}

__device__ __forceinline__ unsigned ldacq(const unsigned* p) {
    unsigned v;
    asm volatile("ld.acquire.gpu.global.u32 %0, [%1];" : "=r"(v) : "l"(p) : "memory");
    return v;
}
__device__ __forceinline__ void strel(unsigned* p, unsigned v) {
    asm volatile("st.release.gpu.global.u32 [%0], %1;" :: "l"(p), "r"(v) : "memory");
}

__device__ __forceinline__ void ldsm_x4(uint32_t& r0, uint32_t& r1, uint32_t& r2, uint32_t& r3,
                                        uint32_t addr) {
    asm volatile("ldmatrix.sync.aligned.m8n8.x4.shared.b16 {%0,%1,%2,%3}, [%4];"
                 : "=r"(r0), "=r"(r1), "=r"(r2), "=r"(r3) : "r"(addr));
}

__device__ __forceinline__ void mma16816(float* c, const uint32_t* a, uint32_t b0, uint32_t b1) {
    asm volatile(
        "mma.sync.aligned.m16n8k16.row.col.f32.f16.f16.f32 "
        "{%0,%1,%2,%3}, {%4,%5,%6,%7}, {%8,%9}, {%0,%1,%2,%3};"
        : "+f"(c[0]), "+f"(c[1]), "+f"(c[2]), "+f"(c[3])
        : "r"(a[0]), "r"(a[1]), "r"(a[2]), "r"(a[3]), "r"(b0), "r"(b1));
}

__device__ __forceinline__ float tanh_fast(float x) {
    float e = __expf(2.0f * x);
    return 1.0f - __fdividef(2.0f, e + 1.0f);
}

// ---------------- init ----------------
__global__ void rnn_init_kernel(const float* __restrict__ x) {
    int i = blockIdx.x * blockDim.x + threadIdx.x;
    int stride = gridDim.x * blockDim.x;
    if (i < BB*HH) ((__half*)g_h)[i] = __ushort_as_half((unsigned short)0);
    for (int j = i; j < TT*NIB*NJB*8; j += stride) ((unsigned*)g_flag)[j] = 0u;
    for (int j = i; j < BB*TT*DIN; j += stride) {
        int d = j & 63;
        int t = (j >> 6) & 511;
        int b = j >> 15;
        g_x[t][b][d] = __float2half_rn(x[j]);
    }
}

// ---------------- persistent RNN kernel ----------------
__global__ void __launch_bounds__(NTH, 1)
rnn_hmma_kernel(const float* __restrict__ Whh, const float* __restrict__ Whx,
                const float* __restrict__ bh,  const float* __restrict__ Why,
                const float* __restrict__ by,  float* __restrict__ out)
{
    extern __shared__ char sm[];
    const uint32_t smb = (uint32_t)__cvta_generic_to_shared(sm);
    const int tid = threadIdx.x, warp = tid >> 5, lane = tid & 31;
    const int cta = blockIdx.x;
    const int jb = cta & 15, ib = cta >> 4;
    const int h_base = jb * HT;
    const int b_base = ib * BT;

    // ---- stage B once ----
    __half* bs = (__half*)(sm + SM_B);
    for (int i = tid; i < HT*HH/2; i += NTH) {
        int n = i >> 9, k = (i & 511) * 2;
        const float* src = &Whh[(size_t)(h_base + n)*HH + k];
        *(__half2*)&bs[n*BSTRIDE_H + k] = __floats2half2_rn(src[0], src[1]);
    }
    for (int i = tid; i < HT*DIN/2; i += NTH) {
        int n = i >> 5, k = (i & 31) * 2;
        *(__half2*)&bs[n*BSTRIDE_H + 1024 + k] =
            __floats2half2_rn(Whx[(h_base + n)*DIN + k], Whx[(h_base + n)*DIN + k + 1]);
    }
    float* bias_s = (float*)(sm + SM_BIAS);
    if (tid < HT) bias_s[tid] = bh[h_base + tid];
    __syncthreads();

    const int half = warp >> 2;
    const int wq   = warp & 3;
    const int wm   = (wq >> 1) * 32;
    const int wn   = (wq & 1) * 32;
    const int grp  = lane >> 2, thr4 = lane & 3;
    const int barid = 1 + half;
    const int ptid = tid & 127;

    // ldsm lane addressing
    const int a_r = (lane & 7) + 8*((lane >> 3) & 1);
    const uint32_t a_rel = (uint32_t)((wm + a_r)*ASTRIDE_B + (lane >> 4)*16);
    const int b_r = (lane & 7) + 8*(lane >> 4);
    const uint32_t b_k2 = (uint32_t)(((lane >> 3) & 1) * 16);
    const uint32_t bB0 = smb + SM_B + (uint32_t)((wn + b_r)*BSTRIDE_B) + b_k2;
    const uint32_t bB1 = bB0 + 16*BSTRIDE_B;

    const int srow = ptid >> 3;
    const int sq   = ptid & 7;

    char* const pA0 = sm + SM_A0;
    char* const pAX = sm + SM_AX;
    char* const pA1 = sm + SM_A1;
    const uint32_t A0 = smb + SM_A0, AX = smb + SM_AX, A1 = smb + SM_A1;

    float acc[2][2][2][4];

    auto stage4 = [&](char* dst, const __half* src, int sstride) {
        #pragma unroll
        for (int rr = 0; rr < 4; ++rr) {
            int r = srow + rr*16;
            cp_async16(dst + r*ASTRIDE_B + sq*16, src + (size_t)r*sstride + sq*8);
        }
        cp_commit();
    };

    auto do_chunk = [&](uint32_t abuf, int g) {   // g = global chunk id (0..16)
        const uint32_t bc = (uint32_t)(g * 128);
        #pragma unroll
        for (int kk = 0; kk < 4; ++kk) {
            uint32_t a0[4], a1[4], b0[4], b1[4];
            ldsm_x4(a0[0],a0[1],a0[2],a0[3], abuf + a_rel + kk*32);
            ldsm_x4(a1[0],a1[1],a1[2],a1[3], abuf + a_rel + 16*ASTRIDE_B + kk*32);
            ldsm_x4(b0[0],b0[1],b0[2],b0[3], bB0 + bc + kk*32);
            ldsm_x4(b1[0],b1[1],b1[2],b1[3], bB1 + bc + kk*32);
            mma16816(acc[0][0][0], a0, b0[0], b0[1]);
            mma16816(acc[0][0][1], a0, b0[2], b0[3]);
            mma16816(acc[0][1][0], a0, b1[0], b1[1]);
            mma16816(acc[0][1][1], a0, b1[2], b1[3]);
            mma16816(acc[1][0][0], a1, b0[0], b0[1]);
            mma16816(acc[1][0][1], a1, b0[2], b0[3]);
            mma16816(acc[1][1][0], a1, b1[0], b1[1]);
            mma16816(acc[1][1][1], a1, b1[2], b1[3]);
        }
    };

    bool alive = true;

    // bounded flag wait (value already prefetched into v; re-poll if 0)
    auto flag_wait = [&](const unsigned* p, unsigned v) {
        if (v) return;
        unsigned spins = 0;
        while (alive) {
            if (ldacq(p)) break;
            if (++spins >= SPIN_BOUND) { alive = false; break; }
        }
    };

    for (int t = 0; t < TT; ++t) {
        const __half* hsrc = &g_h[t & 1][0][0];
        const __half* hrow = hsrc + (size_t)b_base*HH;
        const unsigned* fl = (t > 0) ? &g_flag[t-1][ib][0][0] : nullptr;   // stride 8 per jb

        #pragma unroll
        for (int i = 0; i < 2; ++i)
            #pragma unroll
            for (int j = 0; j < 2; ++j)
                #pragma unroll
                for (int k = 0; k < 2; ++k)
                    #pragma unroll
                    for (int q = 0; q < 4; ++q) acc[i][j][k][q] = 0.f;

        if (half == 0) {
            // x chunk first (h-independent)
            stage4(pAX, &g_x[t][b_base][0], DIN);
            // prologue: chunks i=0..3 -> global (jb+i)&15; own chunk (i=0) needs no flag
            if (t > 0) {
                unsigned f1 = ldacq(fl + ((jb+1)&15)*8);
                unsigned f2 = ldacq(fl + ((jb+2)&15)*8);
                unsigned f3 = ldacq(fl + ((jb+3)&15)*8);
                flag_wait(fl + ((jb+1)&15)*8, f1);
                flag_wait(fl + ((jb+2)&15)*8, f2);
                flag_wait(fl + ((jb+3)&15)*8, f3);
            }
            #pragma unroll
            for (int p = 0; p < 4; ++p)
                stage4(pA0 + p*ABUF_B, hrow + ((jb+p)&15)*KCH, HH);

            cp_wait<4>();
            asm volatile("bar.sync %0, 128;" :: "r"(barid) : "memory");
            do_chunk(AX, 16);

            // in-loop flag prefetch: chunk staged at iter c is i=c+3 (c=1..4)
            const unsigned* fpp = (t > 0) ? fl + ((jb+4)&15)*8 : nullptr;
            unsigned fpre = (t > 0) ? ldacq(fpp) : 1u;
            #pragma unroll
            for (int c = 0; c < 8; ++c) {
                cp_wait_dyn((c == 0) ? 3 : ((c < 6) ? 2 : (7 - c)));
                asm volatile("bar.sync %0, 128;" :: "r"(barid) : "memory");
                if (c >= 1 && c <= 4) {
                    if (t > 0) flag_wait(fpp, fpre);
                    stage4(pA0 + ((c+3) & 3)*ABUF_B, hrow + ((jb+c+3)&15)*KCH, HH);
                    if (c < 4 && t > 0) { fpp = fl + ((jb+c+4)&15)*8; fpre = ldacq(fpp); }
                }
                do_chunk(A0 + (c & 3)*ABUF_B, (jb+c)&15);
            }
        } else {
            // prologue: chunks i=8..11 -> global (jb+8..11)&15
            if (t > 0) {
                unsigned f0 = ldacq(fl + ((jb+8)&15)*8);
                unsigned f1 = ldacq(fl + ((jb+9)&15)*8);
                unsigned f2 = ldacq(fl + ((jb+10)&15)*8);
                unsigned f3 = ldacq(fl + ((jb+11)&15)*8);
                flag_wait(fl + ((jb+8)&15)*8,  f0);
                flag_wait(fl + ((jb+9)&15)*8,  f1);
                flag_wait(fl + ((jb+10)&15)*8, f2);
                flag_wait(fl + ((jb+11)&15)*8, f3);
            }
            #pragma unroll
            for (int p = 0; p < 4; ++p)
                stage4(pA1 + p*ABUF_B, hrow + ((jb+8+p)&15)*KCH, HH);

            const unsigned* fpp = (t > 0) ? fl + ((jb+12)&15)*8 : nullptr;
            unsigned fpre = (t > 0) ? ldacq(fpp) : 1u;
            #pragma unroll
            for (int e = 0; e < 8; ++e) {
                cp_wait_dyn((e == 0) ? 3 : ((e < 6) ? 2 : (7 - e)));
                asm volatile("bar.sync %0, 128;" :: "r"(barid) : "memory");
                if (e >= 1 && e <= 4) {
                    if (t > 0) flag_wait(fpp, fpre);
                    stage4(pA1 + ((e+3) & 3)*ABUF_B, hrow + ((jb+11+e)&15)*KCH, HH);
                    if (e < 4 && t > 0) { fpp = fl + ((jb+12+e)&15)*8; fpre = ldacq(fpp); }
                }
                do_chunk(A1 + (e & 3)*ABUF_B, (jb+8+e)&15);
            }
            // ring dead before partials overwrite
            asm volatile("bar.sync %0, 128;" :: "r"(barid) : "memory");
            char* red = sm + SM_RED + wq*4096;
            #pragma unroll
            for (int s_m = 0; s_m < 2; ++s_m)
                #pragma unroll
                for (int sn = 0; sn < 2; ++sn)
                    #pragma unroll
                    for (int j = 0; j < 2; ++j)
                        *(float4*)(red + (((s_m*2 + sn)*2 + j)*512) + lane*16) =
                            *(float4*)acc[s_m][sn][j];
        }

        __syncthreads();   // partials visible

        if (half == 0) {
            char* red = sm + SM_RED + wq*4096;
            __half* hdst = &g_h[(t + 1) & 1][0][0];
            #pragma unroll
            for (int s_m = 0; s_m < 2; ++s_m)
                #pragma unroll
                for (int sn = 0; sn < 2; ++sn)
                    #pragma unroll
                    for (int j = 0; j < 2; ++j) {
                        float4 p = *(float4*)(red + (((s_m*2 + sn)*2 + j)*512) + lane*16);
                        const float* a = acc[s_m][sn][j];
                        const int lcol = wn + sn*16 + j*8 + 2*thr4;
                        const int col = h_base + lcol;
                        float bl  = bias_s[lcol];
                        float bh2 = bias_s[lcol + 1];
                        const int r = b_base + wm + s_m*16 + grp;
                        __half2 v0 = __floats2half2_rn(tanh_fast(a[0] + p.x + bl),
                                                       tanh_fast(a[1] + p.y + bh2));
                        __half2 v1 = __floats2half2_rn(tanh_fast(a[2] + p.z + bl),
                                                       tanh_fast(a[3] + p.w + bh2));
                        *(__half2*)&hdst[(size_t)r*HH + col]     = v0;
                        *(__half2*)&hdst[(size_t)(r+8)*HH + col] = v1;
                    }
            __threadfence();   // writers' release fences (before the flag store)
        }

        __syncthreads();
        if (tid == 0) strel(&g_flag[t][ib][jb][0], 1u);
    }

    // ---- wait for ALL final-h producers of our read-group, then output ----
    {
        const int ib_read = cta >> 4;     // rows 4cta..4cta+3 live in this ib-group
        if (tid < NJB) {
            const unsigned* p = &g_flag[TT-1][ib_read][tid][0];
            unsigned spins = 0;
            while (alive) {
                if (ldacq(p)) break;
                if (++spins >= SPIN_BOUND) { alive = false; break; }
                __nanosleep(8);
            }
        }
        __syncthreads();
    }

    float* logits = (float*)sm;
    const __half* hf = &g_h[0][0][0];      // TT even -> final h in buffer 0
    for (int d = warp; d < 4*DOUT; d += 8) {
        int row = d / DOUT, col = d % DOUT;
        int b = 4*cta + row;
        const __half* hp = hf + (size_t)b*HH;
        const float* wpw = Why + (size_t)col*HH;
        float s = 0.f;
        for (int k = lane; k < HH; k += 32)
            s += __half2float(hp[k]) * wpw[k];
        #pragma unroll
        for (int o = 16; o; o >>= 1) s += __shfl_down_sync(0xffffffffu, s, o);
        if (lane == 0) logits[d] = s + by[col];
    }
    __syncthreads();
    if (tid < 4) {
        int b = 4*cta + tid;
        float mx = -1e30f;
        for (int c = 0; c < DOUT; ++c) mx = fmaxf(mx, logits[tid*DOUT + c]);
        float e[DOUT], sum = 0.f;
        for (int c = 0; c < DOUT; ++c) { e[c] = expf(logits[tid*DOUT + c] - mx); sum += e[c]; }
        float inv = 1.f / sum;
        for (int c = 0; c < DOUT; ++c) out[b*DOUT + c] = e[c]*inv;
    }
}

extern "C" void kernel_launch(void* const* d_in, const int* in_sizes, int n_in,
                              void* d_out, int out_size) {
    const float* x   = (const float*)d_in[0];
    const float* Whx = (const float*)d_in[1];
    const float* Whh = (const float*)d_in[2];
    const float* bh  = (const float*)d_in[3];
    const float* Why = (const float*)d_in[4];
    const float* by  = (const float*)d_in[5];
    float* out = (float*)d_out;

    cudaFuncSetAttribute(rnn_hmma_kernel,
                         cudaFuncAttributeMaxDynamicSharedMemorySize, SMEM_BYTES);

    rnn_init_kernel<<<4096, 256>>>(x);
    rnn_hmma_kernel<<<GRID, NTH, SMEM_BYTES>>>(Whh, Whx, bh, Why, by, out);
}

// round 16
// speedup vs baseline: 1.4739x; 1.4739x over previous
#include <cuda_runtime.h>
#include <cuda_fp16.h>
#include <math.h>
#include <stdint.h>

// Problem constants
#define BB   256
#define TT   512
#define DIN  64
#define HH   1024
#define DOUT 10

// Config: 128 CTAs (8 batch-tiles x 16 h-tiles), tile 32 batch x 64 h-out.
// 256 threads = 2 K-split halves x 4 warps; warp tile 16x32.
// FULL-DEPTH staging: all 17 A chunks resident in smem (no ring, no exposed L2 latency).
#define GRID 128
#define NTH  256
#define BT   32
#define HT   64
#define KCH  64
#define NIB  8
#define IBW  16

// SMEM layout (bytes)
#define BSTRIDE_H 1096                     // halves per B row (1024 Whh + 64 Whx + 8 pad)
#define BSTRIDE_B (BSTRIDE_H*2)            // 2192 == 4 mod 32 words -> conflict-free ldsm
#define ASTRIDE_B 144                      // A row stride (64 halves + pad)
#define ABUF_B    (BT*ASTRIDE_B)           // 4608 per chunk buffer
#define SM_B      0
#define SM_B_SZ   (HT*BSTRIDE_B)           // 140288
#define SM_A      SM_B_SZ                  // 17 buffers: h0..h15, x=buf16
#define SM_RED    (SM_A + 8*ABUF_B)        // partial-acc overlay on half1 bufs 8,9 (8KB)
#define SM_BIAS   (SM_A + 17*ABUF_B)       // 218624
#define SMEM_BYTES (SM_BIAS + 256)         // 218880 (< 232448 cap)

#define SPIN_BOUND (1u<<20)

// Global scratch (__device__ globals: allocation-free rule)
__device__ __align__(256) __half g_h[2][BB][HH];
__device__ __align__(256) __half g_x[TT][BB][DIN];
__device__ unsigned g_bar[TT][NIB];

// ---------------- helpers ----------------
__device__ __forceinline__ void cp_async16(void* sptr, const void* gptr) {
    uint32_t s = (uint32_t)__cvta_generic_to_shared(sptr);
    asm volatile("cp.async.cg.shared.global [%0], [%1], 16;" :: "r"(s), "l"(gptr));
}
__device__ __forceinline__ void cp_commit() { asm volatile("cp.async.commit_group;"); }
template<int N> __device__ __forceinline__ void cp_wait() {
    asm volatile("cp.async.wait_group %0;" :: "n"(N));
}
__device__ __forceinline__ void cp_wait_dyn(int n) {
    switch (n) {
    case 0: cp_wait<0>(); break; case 1: cp_wait<1>(); break;
    case 2: cp_wait<2>(); break; case 3: cp_wait<3>(); break;
    case 4: cp_wait<4>(); break; case 5: cp_wait<5>(); break;
    case 6: cp_wait<6>(); break; default: cp_wait<7>(); break;
    }
}

__device__ __forceinline__ void ldsm_x4(uint32_t& r0, uint32_t& r1, uint32_t& r2, uint32_t& r3,
                                        uint32_t addr) {
    asm volatile("ldmatrix.sync.aligned.m8n8.x4.shared.b16 {%0,%1,%2,%3}, [%4];"
                 : "=r"(r0), "=r"(r1), "=r"(r2), "=r"(r3) : "r"(addr));
}

__device__ __forceinline__ void mma16816(float* c, const uint32_t* a, uint32_t b0, uint32_t b1) {
    asm volatile(
        "mma.sync.aligned.m16n8k16.row.col.f32.f16.f16.f32 "
        "{%0,%1,%2,%3}, {%4,%5,%6,%7}, {%8,%9}, {%0,%1,%2,%3};"
        : "+f"(c[0]), "+f"(c[1]), "+f"(c[2]), "+f"(c[3])
        : "r"(a[0]), "r"(a[1]), "r"(a[2]), "r"(a[3]), "r"(b0), "r"(b1));
}

__device__ __forceinline__ float tanh_fast(float x) {
    float e = __expf(2.0f * x);
    return 1.0f - __fdividef(2.0f, e + 1.0f);
}

// ---------------- init ----------------
__global__ void rnn_init_kernel(const float* __restrict__ x) {
    int i = blockIdx.x * blockDim.x + threadIdx.x;
    int stride = gridDim.x * blockDim.x;
    if (i < BB*HH) ((__half*)g_h)[i] = __ushort_as_half((unsigned short)0);
    if (i < TT*NIB) ((unsigned*)g_bar)[i] = 0u;
    for (int j = i; j < BB*TT*DIN; j += stride) {
        int d = j & 63;
        int t = (j >> 6) & 511;
        int b = j >> 15;
        g_x[t][b][d] = __float2half_rn(x[j]);
    }
}

// ---------------- persistent RNN kernel ----------------
__global__ void __launch_bounds__(NTH, 1)
rnn_hmma_kernel(const float* __restrict__ Whh, const float* __restrict__ Whx,
                const float* __restrict__ bh,  const float* __restrict__ Why,
                const float* __restrict__ by,  float* __restrict__ out)
{
    extern __shared__ char sm[];
    const uint32_t smb = (uint32_t)__cvta_generic_to_shared(sm);
    const int tid = threadIdx.x, warp = tid >> 5, lane = tid & 31;
    const int cta = blockIdx.x;
    const int jb = cta & 15, ib = cta >> 4;    // 16 h-tiles x 8 b-tiles
    const int h_base = jb * HT;
    const int b_base = ib * BT;

    // ---- stage B once: Whh [64,1024] + Whx [64,64] fp16, row stride 1096 halves ----
    __half* bs = (__half*)(sm + SM_B);
    for (int i = tid; i < HT*HH/2; i += NTH) {
        int n = i >> 9, k = (i & 511) * 2;
        const float* src = &Whh[(size_t)(h_base + n)*HH + k];
        *(__half2*)&bs[n*BSTRIDE_H + k] = __floats2half2_rn(src[0], src[1]);
    }
    for (int i = tid; i < HT*DIN/2; i += NTH) {
        int n = i >> 5, k = (i & 31) * 2;
        *(__half2*)&bs[n*BSTRIDE_H + 1024 + k] =
            __floats2half2_rn(Whx[(h_base + n)*DIN + k], Whx[(h_base + n)*DIN + k + 1]);
    }
    float* bias_s = (float*)(sm + SM_BIAS);
    if (tid < HT) bias_s[tid] = bh[h_base + tid];
    __syncthreads();

    // warp decomposition: half (K-split) x [2m-pairs x 2n], warp tile 16x32
    const int half = warp >> 2;          // 0: x + h chunks 0..7 ; 1: h chunks 8..15
    const int wq   = warp & 3;
    const int wm   = (wq >> 1) * 16;
    const int wn   = (wq & 1) * 32;
    const int grp  = lane >> 2, thr4 = lane & 3;
    const int barid = 1 + half*2 + (wq >> 1);   // pair barriers: ids 1..4
    const int ptid = tid & 63;           // pair-local tid (warps 2p,2p+1 contiguous)

    // ldsm lane addressing
    const int a_r = (lane & 7) + 8*((lane >> 3) & 1);
    const uint32_t a_rel = (uint32_t)((wm + a_r)*ASTRIDE_B + (lane >> 4)*16);
    const int b_r = (lane & 7) + 8*(lane >> 4);
    const uint32_t b_k2 = (uint32_t)(((lane >> 3) & 1) * 16);
    const uint32_t bB0 = smb + SM_B + (uint32_t)((wn + b_r)*BSTRIDE_B) + b_k2;
    const uint32_t bB1 = bB0 + 16*BSTRIDE_B;

    // staging: thread handles rows (sr, sr+8) of its pair's 16 rows, 16B unit sq
    const int sr = wm + (ptid >> 3);
    const int sq = ptid & 7;
    char* const sa0 = sm + SM_A + sr*ASTRIDE_B + sq*16;
    char* const sa1 = sm + SM_A + (sr+8)*ASTRIDE_B + sq*16;
    const uint32_t A0 = smb + SM_A;

    float accA[4][4], accB[4][4];   // 4 n8-tiles x (rows grp, grp+8), split by kk parity

    auto do_chunk = [&](int g) {    // g = global chunk id 0..16 (16 = x cols)
        const uint32_t abuf = A0 + (uint32_t)(g * ABUF_B);
        const uint32_t bc   = (uint32_t)(g * 128);
        #pragma unroll
        for (int kk = 0; kk < 4; ++kk) {
            uint32_t a[4], b0[4], b1[4];
            ldsm_x4(a[0],a[1],a[2],a[3], abuf + a_rel + kk*32);
            ldsm_x4(b0[0],b0[1],b0[2],b0[3], bB0 + bc + kk*32);
            ldsm_x4(b1[0],b1[1],b1[2],b1[3], bB1 + bc + kk*32);
            float (*acc)[4] = (kk & 1) ? accB : accA;
            mma16816(acc[0], a, b0[0], b0[1]);
            mma16816(acc[1], a, b0[2], b0[3]);
            mma16816(acc[2], a, b1[0], b1[1]);
            mma16816(acc[3], a, b1[2], b1[3]);
        }
    };

    bool alive = true;

    for (int t = 0; t < TT; ++t) {
        const __half* hrow = &g_h[t & 1][b_base][0];

        // ---- half0: stage x chunk (h-independent) BEFORE the barrier wait ----
        if (half == 0) {
            const __half* s0 = &g_x[t][b_base + sr][sq*8];
            cp_async16(sa0 + 16*ABUF_B, s0);
            cp_async16(sa1 + 16*ABUF_B, s0 + 8*DIN);
            cp_commit();
        }

        // ---- wait for h_t (our 16-CTA ib-group); single-thread acquire fence ----
        if (t > 0) {
            if (tid == 0) {
                if (alive) {
                    unsigned spins = 0;
                    while (*((volatile unsigned*)&g_bar[t-1][ib]) < IBW) {
                        if (++spins >= SPIN_BOUND) { alive = false; break; }
                        __nanosleep(8);
                    }
                }
                __threadfence();
            }
            __syncthreads();
        }

        #pragma unroll
        for (int j = 0; j < 4; ++j)
            #pragma unroll
            for (int q = 0; q < 4; ++q) { accA[j][q] = 0.f; accB[j][q] = 0.f; }

        if (half == 0) {
            // stage ALL 8 h chunks up-front (full depth, one group each)
            const __half* h0 = hrow + (size_t)sr*HH + sq*8;
            const __half* h1 = hrow + (size_t)(sr+8)*HH + sq*8;
            #pragma unroll
            for (int c = 0; c < 8; ++c) {
                cp_async16(sa0 + c*ABUF_B, h0 + c*KCH);
                cp_async16(sa1 + c*ABUF_B, h1 + c*KCH);
                cp_commit();
            }
            // x first (oldest group)
            cp_wait<8>();
            asm volatile("bar.sync %0, 64;" :: "r"(barid) : "memory");
            do_chunk(16);
            #pragma unroll
            for (int c = 0; c < 8; ++c) {
                cp_wait_dyn(7 - c);
                asm volatile("bar.sync %0, 64;" :: "r"(barid) : "memory");
                do_chunk(c);
            }
        } else {
            const __half* h0 = hrow + (size_t)sr*HH + sq*8;
            const __half* h1 = hrow + (size_t)(sr+8)*HH + sq*8;
            #pragma unroll
            for (int c = 8; c < 16; ++c) {
                cp_async16(sa0 + c*ABUF_B, h0 + c*KCH);
                cp_async16(sa1 + c*ABUF_B, h1 + c*KCH);
                cp_commit();
            }
            #pragma unroll
            for (int e = 0; e < 8; ++e) {
                cp_wait_dyn(7 - e);
                asm volatile("bar.sync %0, 64;" :: "r"(barid) : "memory");
                do_chunk(8 + e);
            }
            // all half1 threads done reading bufs 8,9 before partial overwrite
            asm volatile("bar.sync 5, 128;" ::: "memory");
            char* red = sm + SM_RED + wq*2048;
            #pragma unroll
            for (int j = 0; j < 4; ++j) {
                float4 v = make_float4(accA[j][0]+accB[j][0], accA[j][1]+accB[j][1],
                                       accA[j][2]+accB[j][2], accA[j][3]+accB[j][3]);
                *(float4*)(red + j*512 + lane*16) = v;
            }
        }

        __syncthreads();   // partials visible; all A buffers dead

        if (half == 0) {
            char* red = sm + SM_RED + wq*2048;
            __half* hdst = &g_h[(t + 1) & 1][0][0];
            const int r = b_base + wm + grp;
            #pragma unroll
            for (int j = 0; j < 4; ++j) {
                float4 p = *(float4*)(red + j*512 + lane*16);
                const int lcol = wn + j*8 + 2*thr4;
                const int col = h_base + lcol;
                float bl  = bias_s[lcol];
                float bh2 = bias_s[lcol + 1];
                __half2 v0 = __floats2half2_rn(tanh_fast(accA[j][0]+accB[j][0]+p.x + bl),
                                               tanh_fast(accA[j][1]+accB[j][1]+p.y + bh2));
                __half2 v1 = __floats2half2_rn(tanh_fast(accA[j][2]+accB[j][2]+p.z + bl),
                                               tanh_fast(accA[j][3]+accB[j][3]+p.w + bh2));
                *(__half2*)&hdst[(size_t)r*HH + col]     = v0;
                *(__half2*)&hdst[(size_t)(r+8)*HH + col] = v1;
            }
        }

        // ---- arrive at our ib-group barrier ----
        __syncthreads();
        if (tid == 0) { __threadfence(); atomicAdd(&g_bar[t][ib], 1u); }
    }

    // ---- wait for final h of our ib-group (owns rows 2cta, 2cta+1) ----
    if (tid == 0) {
        if (alive) {
            unsigned spins = 0;
            while (*((volatile unsigned*)&g_bar[TT-1][ib]) < IBW) {
                if (++spins >= SPIN_BOUND) { alive = false; break; }
                __nanosleep(8);
            }
        }
        __threadfence();
    }
    __syncthreads();

    // ---- output: o = h_final @ Why^T + by, softmax (2 batch rows per CTA) ----
    float* logits = (float*)sm;
    const __half* hf = &g_h[0][0][0];      // TT even -> final h in buffer 0
    for (int d = warp; d < 2*DOUT; d += 8) {
        int row = d / DOUT, col = d % DOUT;
        int b = 2*cta + row;
        const __half* hp = hf + (size_t)b*HH;
        const float* wpw = Why + (size_t)col*HH;
        float s = 0.f;
        for (int k = lane; k < HH; k += 32)
            s += __half2float(hp[k]) * wpw[k];
        #pragma unroll
        for (int o = 16; o; o >>= 1) s += __shfl_down_sync(0xffffffffu, s, o);
        if (lane == 0) logits[d] = s + by[col];
    }
    __syncthreads();
    if (tid < 2) {
        int b = 2*cta + tid;
        float mx = -1e30f;
        for (int c = 0; c < DOUT; ++c) mx = fmaxf(mx, logits[tid*DOUT + c]);
        float e[DOUT], sum = 0.f;
        for (int c = 0; c < DOUT; ++c) { e[c] = expf(logits[tid*DOUT + c] - mx); sum += e[c]; }
        float inv = 1.f / sum;
        for (int c = 0; c < DOUT; ++c) out[b*DOUT + c] = e[c]*inv;
    }
}

extern "C" void kernel_launch(void* const* d_in, const int* in_sizes, int n_in,
                              void* d_out, int out_size) {
    const float* x   = (const float*)d_in[0];
    const float* Whx = (const float*)d_in[1];
    const float* Whh = (const float*)d_in[2];
    const float* bh  = (const float*)d_in[3];
    const float* Why = (const float*)d_in[4];
    const float* by  = (const float*)d_in[5];
    float* out = (float*)d_out;

    cudaFuncSetAttribute(rnn_hmma_kernel,
                         cudaFuncAttributeMaxDynamicSharedMemorySize, SMEM_BYTES);

    rnn_init_kernel<<<4096, 256>>>(x);
    rnn_hmma_kernel<<<GRID, NTH, SMEM_BYTES>>>(Whh, Whx, bh, Why, by, out);
}